// round 1
// baseline (speedup 1.0000x reference)
#include <cuda_runtime.h>

#define NNODES 4096
#define FIN 128
#define FOUT 64
#define NHEADS 4
#define HF 256
#define NEG_INF_F (-1e9f)

// ---------------- device scratch (static allocation, allowed) ----------------
__device__ float g_mask[NNODES * NNODES];          // 64MB raw mask
__device__ float g_W[FIN * 512];                   // combined weights: [k][c], c<256 -> proj, else skip^T
__device__ float g_proj[NHEADS * NNODES * FOUT];   // [h][n][o]
__device__ float g_skip[NNODES * HF];              // [n][h*64+o]
__device__ float g_ssrc[NHEADS * NNODES];
__device__ float g_stgt[NHEADS * NNODES];
__device__ float g_rowsum[NNODES];
__device__ float g_rowsq[NNODES];
__device__ float g_colsum[NHEADS * NNODES];
__device__ float g_cinv[NHEADS * NNODES];
__device__ float g_rowmu[NNODES];
__device__ float g_rowis[NNODES];

// ---------------- packed f32x2 helpers ----------------
__device__ __forceinline__ unsigned long long ffma2(unsigned long long a,
                                                    unsigned long long b,
                                                    unsigned long long c) {
    unsigned long long d;
    asm("fma.rn.f32x2 %0, %1, %2, %3;" : "=l"(d) : "l"(a), "l"(b), "l"(c));
    return d;
}
__device__ __forceinline__ unsigned long long dup2(float a) {
    unsigned long long d;
    unsigned int u = __float_as_uint(a);
    asm("mov.b64 %0, {%1, %1};" : "=l"(d) : "r"(u));
    return d;
}
__device__ __forceinline__ float2 unpk(unsigned long long v) {
    unsigned int lo, hi;
    asm("mov.b64 {%0, %1}, %2;" : "=r"(lo), "=r"(hi) : "l"(v));
    return make_float2(__uint_as_float(lo), __uint_as_float(hi));
}

// ---------------- kernel Z: zero accumulators ----------------
__global__ void kZero() {
    int i = blockIdx.x * 256 + threadIdx.x;
    if (i < NHEADS * NNODES) g_colsum[i] = 0.f;
    if (i < NNODES) { g_rowsum[i] = 0.f; g_rowsq[i] = 0.f; }
}

// ---------------- kernel W0: build combined weight [128][512] ----------------
__global__ void kW0(const float* __restrict__ pp, const float* __restrict__ sw) {
    int i = blockIdx.x * 256 + threadIdx.x;   // 65536
    int k = i >> 9, c = i & 511;
    float v;
    if (c < 256) v = pp[(c >> 6) * (FIN * FOUT) + k * FOUT + (c & 63)];
    else         v = sw[(c - 256) * FIN + k];
    g_W[i] = v;
}

// ---------------- kernel P: nodes[4096x128] @ W[128x512] -> proj + skip ------
__global__ __launch_bounds__(256) void kP(const float* __restrict__ nodes) {
    __shared__ float a_s[32 * FIN];
    int t = threadIdx.x;
    int n0 = blockIdx.y * 32;
    int c = blockIdx.x * 256 + t;
#pragma unroll
    for (int r = 0; r < 16; r++) {
        int idx = r * 256 + t;
        a_s[idx] = nodes[n0 * FIN + idx];
    }
    __syncthreads();
    float acc[32];
#pragma unroll
    for (int n = 0; n < 32; n++) acc[n] = 0.f;
    for (int k4 = 0; k4 < 32; k4++) {
        float w0 = g_W[(4 * k4 + 0) * 512 + c];
        float w1 = g_W[(4 * k4 + 1) * 512 + c];
        float w2 = g_W[(4 * k4 + 2) * 512 + c];
        float w3 = g_W[(4 * k4 + 3) * 512 + c];
#pragma unroll
        for (int n = 0; n < 32; n++) {
            float4 a = *(const float4*)&a_s[n * FIN + 4 * k4];
            acc[n] = fmaf(a.x, w0, acc[n]);
            acc[n] = fmaf(a.y, w1, acc[n]);
            acc[n] = fmaf(a.z, w2, acc[n]);
            acc[n] = fmaf(a.w, w3, acc[n]);
        }
    }
    if (c < 256) {
        int h = c >> 6, o = c & 63;
        for (int n = 0; n < 32; n++)
            g_proj[(h * NNODES + n0 + n) * FOUT + o] = acc[n];
    } else {
        int cc = c - 256;
        for (int n = 0; n < 32; n++)
            g_skip[(n0 + n) * HF + cc] = acc[n];
    }
}

// ---------------- kernel S: per-node per-head scalar scores ----------------
__global__ void kS(const float* __restrict__ ssv, const float* __restrict__ stv) {
    int id = blockIdx.x * 256 + threadIdx.x;   // 16384
    int h = id >> 12, n = id & 4095;
    const float4* pr = (const float4*)&g_proj[(h * NNODES + n) * FOUT];
    const float4* a = (const float4*)(ssv + h * FOUT);
    const float4* b = (const float4*)(stv + h * FOUT);
    float s1 = 0.f, s2 = 0.f;
#pragma unroll
    for (int q = 0; q < 16; q++) {
        float4 p = pr[q];
        float4 av = __ldg(&a[q]);
        float4 bv = __ldg(&b[q]);
        s1 += p.x * av.x + p.y * av.y + p.z * av.z + p.w * av.w;
        s2 += p.x * bv.x + p.y * bv.y + p.z * bv.z + p.w * bv.w;
    }
    g_ssrc[id] = s1;
    g_stgt[id] = s2;
}

// ---------------- kernel M: mask + row stats + column exp-sums ----------------
__global__ __launch_bounds__(256) void kM(const float* __restrict__ deg,
                                          const float* __restrict__ bond,
                                          const int* __restrict__ cutp) {
    __shared__ float cs[NHEADS][128];
    int t = threadIdx.x;
    int col = t & 127, half = t >> 7;
    int j0 = blockIdx.x * 128, i0 = blockIdx.y * 128;
    float cut = (float)__ldg(cutp);
    float st[NHEADS], acc[NHEADS];
#pragma unroll
    for (int h = 0; h < NHEADS; h++) {
        st[h] = __ldg(&g_stgt[h * NNODES + j0 + col]);
        acc[h] = 0.f;
    }
    for (int s = 0; s < 64; s++) {
        int gi = i0 + 2 * s + half;
        int g = gi * NNODES + j0 + col;
        float d = deg[g], b = bond[g];
        float wdm = d + b;
        float m = (wdm > 0.f) ? wdm : ((b > cut) ? (b + wdm) : NEG_INF_F);
        g_mask[g] = m;
        float s1 = m, s2 = m * m;
#pragma unroll
        for (int off = 16; off; off >>= 1) {
            s1 += __shfl_down_sync(0xffffffffu, s1, off);
            s2 += __shfl_down_sync(0xffffffffu, s2, off);
        }
        if ((t & 31) == 0) {
            atomicAdd(&g_rowsum[gi], s1);
            atomicAdd(&g_rowsq[gi], s2);
        }
#pragma unroll
        for (int h = 0; h < NHEADS; h++) {
            float x = __ldg(&g_ssrc[h * NNODES + gi]) + st[h];
            float lr = fmaxf(x, 0.2f * x);
            acc[h] += __expf(lr + m);
        }
    }
    if (half == 1) {
#pragma unroll
        for (int h = 0; h < NHEADS; h++) cs[h][col] = acc[h];
    }
    __syncthreads();
    if (half == 0) {
#pragma unroll
        for (int h = 0; h < NHEADS; h++)
            atomicAdd(&g_colsum[h * NNODES + j0 + col], acc[h] + cs[h][col]);
    }
}

// ---------------- kernel R: finalize stats ----------------
__global__ void kR() {
    int i = blockIdx.x * 256 + threadIdx.x;
    if (i < NHEADS * NNODES) g_cinv[i] = 1.0f / g_colsum[i];
    if (i < NNODES) {
        float mu = g_rowsum[i] * (1.0f / NNODES);
        float var = fmaxf(g_rowsq[i] * (1.0f / NNODES) - mu * mu, 0.f);
        g_rowmu[i] = mu;
        g_rowis[i] = rsqrtf(var + 1e-5f);
    }
}

// ---------------- kernel A: fused attn-gen + GEMM + epilogue + mask_ln -------
__global__ __launch_bounds__(256) void kA(float* __restrict__ outp,
                                          float* __restrict__ lnp) {
    __shared__ float at[64 * 68];   // attn transposed: at[j_local][i_local], pad 68
    __shared__ float pr[64 * 64];   // proj tile: pr[j_local][f]
    int t = threadIdx.x;
    int h = blockIdx.x;
    int i0 = blockIdx.y * 64;
    int tx = t & 15, ty = t >> 4;
    int f0 = 4 * tx, iA = 4 * ty;
    int jl = t & 63, rsel = t >> 6;
    unsigned long long a00 = 0ull, a01 = 0ull, a10 = 0ull, a11 = 0ull;
    unsigned long long a20 = 0ull, a21 = 0ull, a30 = 0ull, a31 = 0ull;
    const float* ssb = g_ssrc + h * NNODES;

    for (int jt = 0; jt < 64; jt++) {
        int j0 = jt * 64;
        float stv = __ldg(&g_stgt[h * NNODES + j0 + jl]);
        float cvv = __ldg(&g_cinv[h * NNODES + j0 + jl]);
#pragma unroll 4
        for (int r = 0; r < 16; r++) {
            int iL = 4 * r + rsel;
            int gi = i0 + iL;
            int g = gi * NNODES + j0 + jl;
            float m = g_mask[g];
            float x = __ldg(&ssb[gi]) + stv;
            float lr = fmaxf(x, 0.2f * x);
            float a = __expf(lr + m) * cvv;
            at[jl * 68 + iL] = a;
            if (h == 0) {
                lnp[g] = (m - __ldg(&g_rowmu[gi])) * __ldg(&g_rowis[gi]);
            }
        }
#pragma unroll 4
        for (int r = 0; r < 16; r++) {
            int jr = 4 * r + rsel;
            pr[jr * 64 + jl] = g_proj[(h * NNODES + j0 + jr) * FOUT + jl];
        }
        __syncthreads();
#pragma unroll 8
        for (int kk = 0; kk < 64; kk++) {
            float4 av = *(const float4*)&at[kk * 68 + iA];
            ulonglong2 bv = *(const ulonglong2*)&pr[kk * 64 + f0];
            unsigned long long d0 = dup2(av.x), d1 = dup2(av.y);
            unsigned long long d2 = dup2(av.z), d3 = dup2(av.w);
            a00 = ffma2(d0, bv.x, a00); a01 = ffma2(d0, bv.y, a01);
            a10 = ffma2(d1, bv.x, a10); a11 = ffma2(d1, bv.y, a11);
            a20 = ffma2(d2, bv.x, a20); a21 = ffma2(d2, bv.y, a21);
            a30 = ffma2(d3, bv.x, a30); a31 = ffma2(d3, bv.y, a31);
        }
        __syncthreads();
    }
    // epilogue: + skip, ELU, store
    unsigned long long accs[4][2] = {{a00, a01}, {a10, a11}, {a20, a21}, {a30, a31}};
#pragma unroll
    for (int i = 0; i < 4; i++) {
        int gi = i0 + iA + i;
        float2 lo = unpk(accs[i][0]);
        float2 hi = unpk(accs[i][1]);
        float4 sk = *(const float4*)&g_skip[gi * HF + h * FOUT + f0];
        float v0 = lo.x + sk.x;
        float v1 = lo.y + sk.y;
        float v2 = hi.x + sk.z;
        float v3 = hi.y + sk.w;
        v0 = v0 > 0.f ? v0 : expm1f(v0);
        v1 = v1 > 0.f ? v1 : expm1f(v1);
        v2 = v2 > 0.f ? v2 : expm1f(v2);
        v3 = v3 > 0.f ? v3 : expm1f(v3);
        *(float4*)&outp[gi * HF + h * FOUT + f0] = make_float4(v0, v1, v2, v3);
    }
}

// ---------------- host launch ----------------
extern "C" void kernel_launch(void* const* d_in, const int* in_sizes, int n_in,
                              void* d_out, int out_size) {
    const float* nodes = (const float*)d_in[0];
    const float* deg   = (const float*)d_in[1];
    // d_in[2] = edges_features_distance (unused by the reference)
    const float* bond  = (const float*)d_in[3];
    const float* pp    = (const float*)d_in[4];
    const float* ssv   = (const float*)d_in[5];
    const float* stv   = (const float*)d_in[6];
    const float* sw    = (const float*)d_in[7];
    const int*   cutp  = (const int*)d_in[8];

    float* outp = (float*)d_out;                       // [4096, 256]
    float* lnp  = outp + NNODES * HF;                  // [4096, 4096]

    kZero<<<64, 256>>>();
    kW0<<<256, 256>>>(pp, sw);
    kP<<<dim3(2, 128), 256>>>(nodes);
    kS<<<64, 256>>>(ssv, stv);
    kM<<<dim3(32, 32), 256>>>(deg, bond, cutp);
    kR<<<64, 256>>>();
    kA<<<dim3(4, 64), 256>>>(outp, lnp);
}